// round 16
// baseline (speedup 1.0000x reference)
#include <cuda_runtime.h>
#include <cuda_bf16.h>
#include <cstdint>

#define R 512
#define T 65536
#define KMAX 32

// ---------------- device scratch ----------------
__device__ int   g_tcol[R * KMAX];      // [row][k] raw cols (phase1)
__device__ float g_tval[R * KMAX];
__device__ int   g_pc[R * KMAX];        // [thread][k] translated cols (phase3)
__device__ float g_pv[R * KMAX];
__device__ float g_val[KMAX * R];       // [slot][thread] scheduled ELL
__device__ int   g_col[KMAX * R];       // [slot][thread] smem float-index 0..1023 (2 copies)
__device__ int   g_ovfcol[R * KMAX];    // overflow CSR (normally empty)
__device__ float g_ovfval[R * KMAX];
__device__ int   g_ovfcnt[R];
__device__ int   g_rowof[R];
__device__ float g_states[(size_t)T * R];   // 128 MB; PAIRED layout [t/2][p][2]

// accurate fast tanh: 1 - 2/(e^{2x}+1), ~1e-6 abs err
__device__ __forceinline__ float tanh_acc(float x) {
    float e = __expf(2.0f * x);
    return 1.0f - __fdividef(2.0f, e + 1.0f);
}

// ---------------- templated recurrence body (explicit 2-step) ----------------
template <int NK, bool OVF>
__device__ __forceinline__ float run_loop(const float4* __restrict__ xq,   // [T/2]
                                          float* __restrict__ hbuf,        // [2][1024]
                                          int p, int oc, float w0, float w1)
{
    float rv[NK];
    int   rc[NK];   // byte offsets within one 4KB phase
#pragma unroll
    for (int k = 0; k < NK; ++k) {
        rv[k] = g_val[k * R + p];
        rc[k] = g_col[k * R + p] << 2;
    }
    const int skewidx = 512 | (p & ~31) | ((p + (p >> 5)) & 31);

    float2* myst = (float2*)(g_states) + p;    // paired layout: stride 512 float2/pair
    float4 f4cur = xq[0];                      // x[2t], x[2t+1] .. consumed late
    float4 f4nxt = xq[1];
    float ha = 0.0f, hb = 0.0f;

    for (int tp = 0; tp < T / 2; ++tp) {
        // ---- step A: read phase0, write phase1 ----
        {
            const char* hr = (const char*)hbuf;
            float acc0 = 0.0f, acc1 = 0.0f;
#pragma unroll
            for (int k = 0; k < NK; ++k) {
                float hv = *(const float*)(hr + rc[k]);
                if (k & 1) acc1 = fmaf(rv[k], hv, acc1);
                else       acc0 = fmaf(rv[k], hv, acc0);
            }
            if (OVF) {
                for (int k = 0; k < oc; ++k)
                    acc0 = fmaf(g_ovfval[p * KMAX + k],
                                ((const float*)hr)[g_ovfcol[p * KMAX + k]], acc0);
            }
            acc0 = fmaf(w0, f4cur.x, acc0);    // x consumed late; LDG long hidden
            acc1 = fmaf(w1, f4cur.y, acc1);
            ha = tanh_acc(acc0 + acc1);
            hbuf[1024 + p] = ha;               // copy0 (phase1)
            hbuf[1024 + skewidx] = ha;         // copy1 (skewed, conflict-free)
        }
        float4 f4new = xq[(tp + 2) & (T / 2 - 1)];   // one LDG.128 per 2 steps
        asm volatile("bar.sync 0;" ::: "memory");

        // ---- step B: read phase1, write phase0 ----
        {
            const char* hr = (const char*)hbuf + 4096;
            float acc0 = 0.0f, acc1 = 0.0f;
#pragma unroll
            for (int k = 0; k < NK; ++k) {
                float hv = *(const float*)(hr + rc[k]);
                if (k & 1) acc1 = fmaf(rv[k], hv, acc1);
                else       acc0 = fmaf(rv[k], hv, acc0);
            }
            if (OVF) {
                for (int k = 0; k < oc; ++k)
                    acc0 = fmaf(g_ovfval[p * KMAX + k],
                                ((const float*)hr)[g_ovfcol[p * KMAX + k]], acc0);
            }
            acc0 = fmaf(w0, f4cur.z, acc0);
            acc1 = fmaf(w1, f4cur.w, acc1);
            hb = tanh_acc(acc0 + acc1);
            hbuf[p] = hb;                      // copy0 (phase0)
            hbuf[skewidx] = hb;                // copy1
        }
        *myst = make_float2(ha, hb);           // ONE STG.64 per 2 steps
        myst += R;
        f4cur = f4nxt;                         // rotate prefetch pipeline
        f4nxt = f4new;
        asm volatile("bar.sync 0;" ::: "memory");
    }
    return hb;
}

// ---------------- fused kernel: extract + schedule + sequential recurrence ----------------
__global__ void __launch_bounds__(R, 1) esn_recur_fused(
    const float* __restrict__ x,
    const float* __restrict__ h0,
    const float* __restrict__ Win,
    const float* __restrict__ W,
    float*       __restrict__ hfinal,
    int write_hfinal)
{
    __shared__ int   s_len[R];
    __shared__ int   s_thr[R];        // original row -> owning thread
    __shared__ int   s_rowof[R];      // sorted position -> original row
    __shared__ int   s_cnt[KMAX + 1];
    __shared__ int   s_base[KMAX + 1];
    __shared__ int   s_wclass[R / 32];
    __shared__ int   s_anyovf;
    __shared__ float hbuf[2 * 1024];  // [phase][copy0:512 | copy1:512]

    const int p = threadIdx.x;

    // ---- phase 1: per-row nnz scan ----
    int len = 0;
    for (int j = 0; j < R; ++j) {
        float v = W[p * R + j];
        if (v != 0.0f) {
            if (len < KMAX) { g_tcol[p * KMAX + len] = j; g_tval[p * KMAX + len] = v; }
            ++len;
        }
    }
    if (len > KMAX) len = KMAX;
    s_len[p] = len;
    if (p <= KMAX) s_cnt[p] = 0;
    if (p == 0) s_anyovf = 0;
    __syncthreads();

    // ---- phase 2: counting sort by len (ascending) ----
    atomicAdd(&s_cnt[len], 1);
    __syncthreads();
    if (p == 0) {
        int acc = 0;
        for (int l = 0; l <= KMAX; ++l) { s_base[l] = acc; acc += s_cnt[l]; }
    }
    __syncthreads();
    int pos = atomicAdd(&s_base[len], 1);
    s_rowof[pos] = p;
    __syncthreads();

    // ---- phase 3a: SNAKE deal of sorted rows to threads (balances entries/warp) ----
    // round r = lane (0..31); within round, warps take rows boustrophedon.
    const int wdx  = p >> 5, lane = p & 31;
    const int i16  = (lane & 1) ? (15 - wdx) : wdx;
    const int q    = lane * 16 + i16;          // my sorted index
    const int row  = s_rowof[q];
    const int mylen = s_len[row];
    g_rowof[p] = row;
    s_thr[row] = p;                            // row -> thread LUT
    __syncthreads();

    // ---- phase 3b: thread p builds its translated (thread-space) entry list ----
    for (int k = 0; k < mylen; ++k) {
        g_pc[p * KMAX + k] = s_thr[g_tcol[row * KMAX + k]];
        g_pv[p * KMAX + k] = g_tval[row * KMAX + k];
    }
    g_ovfcnt[p] = 0;
    s_len[p] = mylen;               // now thread-indexed
    __syncthreads();

    // ---- phase 4: lane 0 of each warp schedules with TWO bank choices per entry ----
    //   copy0: index c        -> bank  c & 31
    //   copy1: index 512+skew -> bank (c + (c>>5)) & 31
    if ((p & 31) == 0) {
        const int base = p;
        int      lens[32];
        unsigned taken[32];
        int total = 0;
        for (int i = 0; i < 32; ++i) {
            lens[i] = s_len[base + i];
            taken[i] = 0u;
            total += lens[i];
        }
        int s = 0;
        while (total > 0 && s < KMAX) {
            unsigned bankused = 0;
            int bankaddr[32];
            int aaddr[32];
            float aval[32];
            for (int i = 0; i < 32; ++i) {
                aaddr[i] = -1;
                const int li = lens[i];
                for (int e = 0; e < li; ++e) {
                    if ((taken[i] >> e) & 1u) continue;
                    int c  = g_pc[(base + i) * KMAX + e];
                    int b0 = c & 31;
                    int a0 = c;
                    int b1 = (c + (c >> 5)) & 31;
                    int a1 = 512 | (c & ~31) | b1;
                    int ub, ua;
                    if (!((bankused >> b0) & 1u) || bankaddr[b0] == a0) { ub = b0; ua = a0; }
                    else if (!((bankused >> b1) & 1u) || bankaddr[b1] == a1) { ub = b1; ua = a1; }
                    else continue;
                    bankused |= 1u << ub;
                    bankaddr[ub] = ua;
                    taken[i] |= 1u << e;
                    aaddr[i] = ua;
                    aval[i]  = g_pv[(base + i) * KMAX + e];
                    --total;
                    break;
                }
            }
            int fb = 0;
            for (int i = 0; i < 32; ++i) {
                if (aaddr[i] >= 0) {
                    g_col[s * R + base + i] = aaddr[i];
                    g_val[s * R + base + i] = aval[i];
                } else {
                    while ((bankused >> fb) & 1u) ++fb;     // always enough free banks
                    bankused |= 1u << fb;
                    g_col[s * R + base + i] = fb;           // copy0 index fb -> bank fb
                    g_val[s * R + base + i] = 0.0f;
                }
            }
            ++s;
        }
        if (total > 0) {            // pathological leftovers -> overflow CSR
            for (int i = 0; i < 32; ++i) {
                int oc = 0;
                for (int e = 0; e < lens[i]; ++e) {
                    if (!((taken[i] >> e) & 1u)) {
                        g_ovfcol[(base + i) * KMAX + oc] = g_pc[(base + i) * KMAX + e];
                        g_ovfval[(base + i) * KMAX + oc] = g_pv[(base + i) * KMAX + e];
                        ++oc;
                    }
                }
                g_ovfcnt[base + i] = oc;
            }
            s_anyovf = 1;           // benign race (same value)
        }
        int cls = s;
        if (cls < 1) cls = 1;
        if (cls > 16) { cls = (cls + 3) & ~3; if (cls > KMAX) cls = KMAX; }
        // pad rounding slots (lane i -> bank i, conflict-free)
        for (int ss = s; ss < cls; ++ss)
            for (int i = 0; i < 32; ++i) {
                g_col[ss * R + base + i] = i;
                g_val[ss * R + base + i] = 0.0f;
            }
        s_wclass[base >> 5] = cls;
    }
    __syncthreads();

    // ---- recurrence ----
    const float w0 = Win[row * 2 + 0];
    const float w1 = Win[row * 2 + 1];
    const int oc   = g_ovfcnt[p];
    const int anyo = s_anyovf;
    const int cls  = s_wclass[p >> 5];

    float h0v = h0[row];
    hbuf[p] = h0v;
    hbuf[512 | (p & ~31) | ((p + (p >> 5)) & 31)] = h0v;
    __syncthreads();

    const float4* xq = (const float4*)x;
    float hn;
#define RLC(NKv) case NKv: \
        hn = anyo ? run_loop<NKv, true >(xq, hbuf, p, oc, w0, w1) \
                  : run_loop<NKv, false>(xq, hbuf, p, oc, w0, w1); break;
    switch (cls) {
        RLC(1)  RLC(2)  RLC(3)  RLC(4)  RLC(5)  RLC(6)  RLC(7)  RLC(8)
        RLC(9)  RLC(10) RLC(11) RLC(12) RLC(13) RLC(14) RLC(15) RLC(16)
        RLC(20) RLC(24) RLC(28)
        default:
            hn = anyo ? run_loop<32, true >(xq, hbuf, p, oc, w0, w1)
                      : run_loop<32, false>(xq, hbuf, p, oc, w0, w1); break;
    }
#undef RLC

    if (write_hfinal) hfinal[row] = hn;   // un-permute once
}

// ---------------- readout GEMV (paired, permuted states), half-grid per launch ----------------
__global__ void __launch_bounds__(256) esn_readout(
    const float* __restrict__ Wout,
    const float* __restrict__ bias,
    float*       __restrict__ out,
    int tbase)
{
    __shared__ float w0s[R];
    __shared__ float w1s[R];
    const int tid = threadIdx.x;
    for (int j = tid; j < R; j += 256) {
        int row = g_rowof[j];
        w0s[j] = Wout[row];
        w1s[j] = Wout[R + row];
    }
    __syncthreads();

    const int warp = tid >> 5;
    const int lane = tid & 31;
    const size_t t = (size_t)tbase + (size_t)blockIdx.x * 8 + warp;
    if (t >= T) return;

    // paired layout: value of h_t[j] at g_states[(t>>1)*1024 + j*2 + (t&1)]
    const float* __restrict__ s = g_states + (t >> 1) * 1024 + (t & 1);
    float a0 = 0.0f, a1 = 0.0f;
#pragma unroll
    for (int k = 0; k < R / 32; ++k) {
        int j = lane + 32 * k;
        float v = s[j * 2];
        a0 += v * w0s[j];
        a1 += v * w1s[j];
    }
#pragma unroll
    for (int o = 16; o; o >>= 1) {
        a0 += __shfl_down_sync(0xFFFFFFFFu, a0, o);
        a1 += __shfl_down_sync(0xFFFFFFFFu, a1, o);
    }
    if (lane == 0) {
        out[2 * t + 0] = a0 + bias[0];
        out[2 * t + 1] = a1 + bias[1];
    }
}

// ---------------- launch ----------------
extern "C" void kernel_launch(void* const* d_in, const int* in_sizes, int n_in,
                              void* d_out, int out_size)
{
    const float* x    = (const float*)d_in[0];
    const float* h0   = (const float*)d_in[1];
    const float* Win  = (const float*)d_in[2];
    const float* W    = (const float*)d_in[3];
    const float* Wout = (const float*)d_in[4];
    const float* bias = (const float*)d_in[5];

    float* out = (float*)d_out;
    const int need_hf = (out_size >= T * 2 + R) ? 1 : 0;
    float* hfinal = out + (size_t)T * 2;

    esn_recur_fused<<<1, R>>>(x, h0, Win, W, need_hf ? hfinal : out, need_hf);
    esn_readout<<<(T / 2) / 8, 256>>>(Wout, bias, out, 0);
    esn_readout<<<(T / 2) / 8, 256>>>(Wout, bias, out, T / 2);
}

// round 17
// speedup vs baseline: 1.4268x; 1.4268x over previous
#include <cuda_runtime.h>
#include <cuda_bf16.h>
#include <cstdint>

#define R 512
#define T 65536
#define KMAX 32

// ---------------- device scratch ----------------
__device__ int   g_tcol[R * KMAX];      // [row][k] raw cols (phase1)
__device__ float g_tval[R * KMAX];
__device__ int   g_pc[R * KMAX];        // [thread][k] translated cols (phase3)
__device__ float g_pv[R * KMAX];
__device__ float g_val[KMAX * R];       // [slot][thread] scheduled ELL
__device__ int   g_col[KMAX * R];       // [slot][thread] smem float-index 0..1023 (2 copies)
__device__ int   g_ovfcol[R * KMAX];    // overflow CSR (normally empty)
__device__ float g_ovfval[R * KMAX];
__device__ int   g_ovfcnt[R];
__device__ int   g_rowof[R];
__device__ float g_states[(size_t)T * R];   // 128 MB; PAIRED layout [t/2][p][2]

// hardware tanh: single MUFU op (~5.6e-4 max abs err; empirically amplifies to
// ~2-3e-4 rel_err through this contracting recurrence — anchor: 1e-6 -> 4.9e-7)
__device__ __forceinline__ float tanh_fast(float x) {
    float r;
    asm("tanh.approx.f32 %0, %1;" : "=f"(r) : "f"(x));
    return r;
}

// ---------------- templated recurrence body (explicit 2-step) ----------------
template <int NK, bool OVF>
__device__ __forceinline__ float run_loop(const float4* __restrict__ xq,   // [T/2]
                                          float* __restrict__ hbuf,        // [2][1024]
                                          int p, int oc, float w0, float w1)
{
    float rv[NK];
    int   rc[NK];   // byte offsets within one 4KB phase
#pragma unroll
    for (int k = 0; k < NK; ++k) {
        rv[k] = g_val[k * R + p];
        rc[k] = g_col[k * R + p] << 2;
    }
    const int skewidx = 512 | (p & ~31) | ((p + (p >> 5)) & 31);

    float2* myst = (float2*)(g_states) + p;    // paired layout: stride 512 float2/pair
    float4 f4cur = xq[0];                      // x[2t], x[2t+1] .. consumed late
    float4 f4nxt = xq[1];
    float ha = 0.0f, hb = 0.0f;

    for (int tp = 0; tp < T / 2; ++tp) {
        // ---- step A: read phase0, write phase1 ----
        {
            const char* hr = (const char*)hbuf;
            float acc0 = 0.0f, acc1 = 0.0f;
#pragma unroll
            for (int k = 0; k < NK; ++k) {
                float hv = *(const float*)(hr + rc[k]);
                if (k & 1) acc1 = fmaf(rv[k], hv, acc1);
                else       acc0 = fmaf(rv[k], hv, acc0);
            }
            if (OVF) {
                for (int k = 0; k < oc; ++k)
                    acc0 = fmaf(g_ovfval[p * KMAX + k],
                                ((const float*)hr)[g_ovfcol[p * KMAX + k]], acc0);
            }
            acc0 = fmaf(w0, f4cur.x, acc0);    // x consumed late; LDG long hidden
            acc1 = fmaf(w1, f4cur.y, acc1);
            ha = tanh_fast(acc0 + acc1);
            hbuf[1024 + p] = ha;               // copy0 (phase1)
            hbuf[1024 + skewidx] = ha;         // copy1 (skewed, conflict-free)
        }
        float4 f4new = xq[(tp + 2) & (T / 2 - 1)];   // one LDG.128 per 2 steps
        asm volatile("bar.sync 0;" ::: "memory");

        // ---- step B: read phase1, write phase0 ----
        {
            const char* hr = (const char*)hbuf + 4096;
            float acc0 = 0.0f, acc1 = 0.0f;
#pragma unroll
            for (int k = 0; k < NK; ++k) {
                float hv = *(const float*)(hr + rc[k]);
                if (k & 1) acc1 = fmaf(rv[k], hv, acc1);
                else       acc0 = fmaf(rv[k], hv, acc0);
            }
            if (OVF) {
                for (int k = 0; k < oc; ++k)
                    acc0 = fmaf(g_ovfval[p * KMAX + k],
                                ((const float*)hr)[g_ovfcol[p * KMAX + k]], acc0);
            }
            acc0 = fmaf(w0, f4cur.z, acc0);
            acc1 = fmaf(w1, f4cur.w, acc1);
            hb = tanh_fast(acc0 + acc1);
            hbuf[p] = hb;                      // copy0 (phase0)
            hbuf[skewidx] = hb;                // copy1
        }
        *myst = make_float2(ha, hb);           // ONE STG.64 per 2 steps
        myst += R;
        f4cur = f4nxt;                         // rotate prefetch pipeline
        f4nxt = f4new;
        asm volatile("bar.sync 0;" ::: "memory");
    }
    return hb;
}

// ---------------- fused kernel: extract + schedule + sequential recurrence ----------------
__global__ void __launch_bounds__(R, 1) esn_recur_fused(
    const float* __restrict__ x,
    const float* __restrict__ h0,
    const float* __restrict__ Win,
    const float* __restrict__ W,
    float*       __restrict__ hfinal,
    int write_hfinal)
{
    __shared__ int   s_len[R];
    __shared__ int   s_pos[R];
    __shared__ int   s_rowof[R];
    __shared__ int   s_cnt[KMAX + 1];
    __shared__ int   s_base[KMAX + 1];
    __shared__ int   s_wclass[R / 32];
    __shared__ int   s_anyovf;
    __shared__ float hbuf[2 * 1024];      // [phase][copy0:512 | copy1:512]

    const int p = threadIdx.x;

    // ---- phase 1: per-row nnz scan ----
    int len = 0;
    for (int j = 0; j < R; ++j) {
        float v = W[p * R + j];
        if (v != 0.0f) {
            if (len < KMAX) { g_tcol[p * KMAX + len] = j; g_tval[p * KMAX + len] = v; }
            ++len;
        }
    }
    if (len > KMAX) len = KMAX;
    s_len[p] = len;
    if (p <= KMAX) s_cnt[p] = 0;
    if (p == 0) s_anyovf = 0;
    __syncthreads();

    // ---- phase 2: counting sort by len (ascending) ----
    atomicAdd(&s_cnt[len], 1);
    __syncthreads();
    if (p == 0) {
        int acc = 0;
        for (int l = 0; l <= KMAX; ++l) { s_base[l] = acc; acc += s_cnt[l]; }
    }
    __syncthreads();
    int pos = atomicAdd(&s_base[len], 1);
    s_pos[p] = pos;
    s_rowof[pos] = p;
    __syncthreads();

    // ---- phase 3: thread p builds its translated entry list ----
    const int row   = s_rowof[p];
    const int mylen = s_len[row];
    g_rowof[p] = row;
    for (int k = 0; k < mylen; ++k) {
        g_pc[p * KMAX + k] = s_pos[g_tcol[row * KMAX + k]];
        g_pv[p * KMAX + k] = g_tval[row * KMAX + k];
    }
    g_ovfcnt[p] = 0;
    s_len[p] = mylen;               // now thread-indexed
    __syncthreads();

    // ---- phase 4: lane 0 of each warp schedules with TWO bank choices per entry ----
    //   copy0: index c        -> bank  c & 31
    //   copy1: index 512+skew -> bank (c + (c>>5)) & 31
    if ((p & 31) == 0) {
        const int base = p;
        int      lens[32];
        unsigned taken[32];
        int total = 0;
        for (int i = 0; i < 32; ++i) {
            lens[i] = s_len[base + i];
            taken[i] = 0u;
            total += lens[i];
        }
        int s = 0;
        while (total > 0 && s < KMAX) {
            unsigned bankused = 0;
            int bankaddr[32];
            int aaddr[32];
            float aval[32];
            for (int i = 0; i < 32; ++i) {
                aaddr[i] = -1;
                const int li = lens[i];
                for (int e = 0; e < li; ++e) {
                    if ((taken[i] >> e) & 1u) continue;
                    int c  = g_pc[(base + i) * KMAX + e];
                    int b0 = c & 31;
                    int a0 = c;
                    int b1 = (c + (c >> 5)) & 31;
                    int a1 = 512 | (c & ~31) | b1;
                    int ub, ua;
                    if (!((bankused >> b0) & 1u) || bankaddr[b0] == a0) { ub = b0; ua = a0; }
                    else if (!((bankused >> b1) & 1u) || bankaddr[b1] == a1) { ub = b1; ua = a1; }
                    else continue;
                    bankused |= 1u << ub;
                    bankaddr[ub] = ua;
                    taken[i] |= 1u << e;
                    aaddr[i] = ua;
                    aval[i]  = g_pv[(base + i) * KMAX + e];
                    --total;
                    break;
                }
            }
            int fb = 0;
            for (int i = 0; i < 32; ++i) {
                if (aaddr[i] >= 0) {
                    g_col[s * R + base + i] = aaddr[i];
                    g_val[s * R + base + i] = aval[i];
                } else {
                    while ((bankused >> fb) & 1u) ++fb;     // always enough free banks
                    bankused |= 1u << fb;
                    g_col[s * R + base + i] = fb;           // copy0 index fb -> bank fb
                    g_val[s * R + base + i] = 0.0f;
                }
            }
            ++s;
        }
        if (total > 0) {            // pathological leftovers -> overflow CSR
            for (int i = 0; i < 32; ++i) {
                int oc = 0;
                for (int e = 0; e < lens[i]; ++e) {
                    if (!((taken[i] >> e) & 1u)) {
                        g_ovfcol[(base + i) * KMAX + oc] = g_pc[(base + i) * KMAX + e];
                        g_ovfval[(base + i) * KMAX + oc] = g_pv[(base + i) * KMAX + e];
                        ++oc;
                    }
                }
                g_ovfcnt[base + i] = oc;
            }
            s_anyovf = 1;           // benign race (same value)
        }
        int cls = s;
        if (cls < 1) cls = 1;
        if (cls > 16) { cls = (cls + 3) & ~3; if (cls > KMAX) cls = KMAX; }
        // pad rounding slots (lane i -> bank i, conflict-free)
        for (int ss = s; ss < cls; ++ss)
            for (int i = 0; i < 32; ++i) {
                g_col[ss * R + base + i] = i;
                g_val[ss * R + base + i] = 0.0f;
            }
        s_wclass[base >> 5] = cls;
    }
    __syncthreads();

    // ---- recurrence ----
    const float w0 = Win[row * 2 + 0];
    const float w1 = Win[row * 2 + 1];
    const int oc   = g_ovfcnt[p];
    const int anyo = s_anyovf;
    const int cls  = s_wclass[p >> 5];

    float h0v = h0[row];
    hbuf[p] = h0v;
    hbuf[512 | (p & ~31) | ((p + (p >> 5)) & 31)] = h0v;
    __syncthreads();

    const float4* xq = (const float4*)x;
    float hn;
#define RLC(NKv) case NKv: \
        hn = anyo ? run_loop<NKv, true >(xq, hbuf, p, oc, w0, w1) \
                  : run_loop<NKv, false>(xq, hbuf, p, oc, w0, w1); break;
    switch (cls) {
        RLC(1)  RLC(2)  RLC(3)  RLC(4)  RLC(5)  RLC(6)  RLC(7)  RLC(8)
        RLC(9)  RLC(10) RLC(11) RLC(12) RLC(13) RLC(14) RLC(15) RLC(16)
        RLC(20) RLC(24) RLC(28)
        default:
            hn = anyo ? run_loop<32, true >(xq, hbuf, p, oc, w0, w1)
                      : run_loop<32, false>(xq, hbuf, p, oc, w0, w1); break;
    }
#undef RLC

    if (write_hfinal) hfinal[row] = hn;   // un-permute once
}

// ---------------- readout GEMV (paired, permuted states), half-grid per launch ----------------
__global__ void __launch_bounds__(256) esn_readout(
    const float* __restrict__ Wout,
    const float* __restrict__ bias,
    float*       __restrict__ out,
    int tbase)
{
    __shared__ float w0s[R];
    __shared__ float w1s[R];
    const int tid = threadIdx.x;
    for (int j = tid; j < R; j += 256) {
        int row = g_rowof[j];
        w0s[j] = Wout[row];
        w1s[j] = Wout[R + row];
    }
    __syncthreads();

    const int warp = tid >> 5;
    const int lane = tid & 31;
    const size_t t = (size_t)tbase + (size_t)blockIdx.x * 8 + warp;
    if (t >= T) return;

    // paired layout: value of h_t[j] at g_states[(t>>1)*1024 + j*2 + (t&1)]
    const float* __restrict__ s = g_states + (t >> 1) * 1024 + (t & 1);
    float a0 = 0.0f, a1 = 0.0f;
#pragma unroll
    for (int k = 0; k < R / 32; ++k) {
        int j = lane + 32 * k;
        float v = s[j * 2];
        a0 += v * w0s[j];
        a1 += v * w1s[j];
    }
#pragma unroll
    for (int o = 16; o; o >>= 1) {
        a0 += __shfl_down_sync(0xFFFFFFFFu, a0, o);
        a1 += __shfl_down_sync(0xFFFFFFFFu, a1, o);
    }
    if (lane == 0) {
        out[2 * t + 0] = a0 + bias[0];
        out[2 * t + 1] = a1 + bias[1];
    }
}

// ---------------- launch ----------------
extern "C" void kernel_launch(void* const* d_in, const int* in_sizes, int n_in,
                              void* d_out, int out_size)
{
    const float* x    = (const float*)d_in[0];
    const float* h0   = (const float*)d_in[1];
    const float* Win  = (const float*)d_in[2];
    const float* W    = (const float*)d_in[3];
    const float* Wout = (const float*)d_in[4];
    const float* bias = (const float*)d_in[5];

    float* out = (float*)d_out;
    const int need_hf = (out_size >= T * 2 + R) ? 1 : 0;
    float* hfinal = out + (size_t)T * 2;

    esn_recur_fused<<<1, R>>>(x, h0, Win, W, need_hf ? hfinal : out, need_hf);
    esn_readout<<<(T / 2) / 8, 256>>>(Wout, bias, out, 0);
    esn_readout<<<(T / 2) / 8, 256>>>(Wout, bias, out, T / 2);
}